// round 10
// baseline (speedup 1.0000x reference)
#include <cuda_runtime.h>
#include <cuda_bf16.h>
#include <math.h>

// Problem constants
#define NB   64     // batch
#define TT   512    // time steps
#define DD   512    // input dim
#define HH   512    // hidden dim
#define G4   2048   // 4*H

typedef unsigned long long u64;

// ---------------------------------------------------------------------------
// Packed f32x2 helpers (sm_103a FFMA2 — ptxas never auto-generates these)
// ---------------------------------------------------------------------------
__device__ __forceinline__ u64 pack_dup(float v)
{
    u64 r; asm("mov.b64 %0, {%1, %1};" : "=l"(r) : "f"(v)); return r;
}
__device__ __forceinline__ void ffma2(u64& acc, u64 a, u64 b)
{
    asm("fma.rn.f32x2 %0, %1, %2, %0;" : "+l"(acc) : "l"(a), "l"(b));
}
__device__ __forceinline__ float2 unpk(u64 v)
{
    float2 r; asm("mov.b64 {%0, %1}, %2;" : "=f"(r.x), "=f"(r.y) : "l"(v)); return r;
}

// ---------------------------------------------------------------------------
// Scratch (device globals: the sanctioned no-alloc workaround)
// ---------------------------------------------------------------------------
#define NCTA 128
#define FLAG_STRIDE 32   // 128B between flags -> distinct L2 lines/slices

__device__ float    g_xh[(size_t)TT * NB * G4];   // (T, N, 4H) pre-projected gates
__device__ unsigned g_flag[NCTA * FLAG_STRIDE];   // per-CTA step flags, padded

// ---------------------------------------------------------------------------
// Kernel 1: xh = x @ W_xh + (b_xh + b_hh)   — FFMA2 inner loop (unchanged)
// ---------------------------------------------------------------------------
#define BM 128
#define BN 128
#define BK 8

__global__ __launch_bounds__(256, 2)
void gemm_xh_kernel(const float* __restrict__ x,
                    const float* __restrict__ Wxh,
                    const float* __restrict__ bxh,
                    const float* __restrict__ bhh)
{
    __shared__ float As[BK][BM];   // transposed A tile
    __shared__ float Bs[BK][BN];

    const int tid = threadIdx.x;
    const int bm  = blockIdx.y;
    const int bn  = blockIdx.x;

    const int warp = tid >> 5, lane = tid & 31;
    const int wm = warp >> 1, wn = warp & 1;
    const int tm = lane & 3,  tn = lane >> 2;
    const int m0 = wm * 32 + tm * 8;
    const int n0 = wn * 64 + tn * 8;

    const int ar = tid >> 1;
    const int aq = tid & 1;
    const int gm = bm * BM + ar;            // global row m = t*64+n
    const int t  = gm >> 6;
    const int nn = gm & 63;
    const float* __restrict__ arow = x + ((size_t)nn * TT + t) * DD;

    const int rb = tid >> 5;
    const int cb = (tid & 31) * 4;
    const float* __restrict__ bcol = Wxh + (size_t)bn * BN + cb;

    u64 acc2[8][4];
#pragma unroll
    for (int i = 0; i < 8; i++)
#pragma unroll
        for (int j = 0; j < 4; j++) acc2[i][j] = 0ull;

    for (int k0 = 0; k0 < DD; k0 += BK) {
        const float4 av = *(const float4*)(arow + k0 + aq * 4);
        const float4 bv = *(const float4*)(bcol + (size_t)(k0 + rb) * G4);
        __syncthreads();
        As[aq * 4 + 0][ar] = av.x;
        As[aq * 4 + 1][ar] = av.y;
        As[aq * 4 + 2][ar] = av.z;
        As[aq * 4 + 3][ar] = av.w;
        *(float4*)&Bs[rb][cb] = bv;
        __syncthreads();

#pragma unroll
        for (int kk = 0; kk < BK; kk++) {
            float ra[8];
            *(float4*)&ra[0] = *(const float4*)&As[kk][m0];
            *(float4*)&ra[4] = *(const float4*)&As[kk][m0 + 4];
            const ulonglong2 b01 = *(const ulonglong2*)&Bs[kk][n0];
            const ulonglong2 b23 = *(const ulonglong2*)&Bs[kk][n0 + 4];
#pragma unroll
            for (int i = 0; i < 8; i++) {
                const u64 ai = pack_dup(ra[i]);
                ffma2(acc2[i][0], ai, b01.x);
                ffma2(acc2[i][1], ai, b01.y);
                ffma2(acc2[i][2], ai, b23.x);
                ffma2(acc2[i][3], ai, b23.y);
            }
        }
    }

    const int col0 = bn * BN + n0;
    float bsum[8];
#pragma unroll
    for (int j = 0; j < 8; j++)
        bsum[j] = bxh[col0 + j] + bhh[col0 + j];

#pragma unroll
    for (int i = 0; i < 8; i++) {
        const size_t row = (size_t)(bm * BM + m0 + i);
        float* p = g_xh + row * G4 + col0;
        float2 c0 = unpk(acc2[i][0]);
        float2 c1 = unpk(acc2[i][1]);
        float2 c2 = unpk(acc2[i][2]);
        float2 c3 = unpk(acc2[i][3]);
        float4 v0 = make_float4(c0.x + bsum[0], c0.y + bsum[1],
                                c1.x + bsum[2], c1.y + bsum[3]);
        float4 v1 = make_float4(c2.x + bsum[4], c2.y + bsum[5],
                                c3.x + bsum[6], c3.y + bsum[7]);
        *(float4*)p       = v0;
        *(float4*)(p + 4) = v1;
    }
}

// ---------------------------------------------------------------------------
// Kernel 2: flag reset (keeps graph replays deterministic)
// ---------------------------------------------------------------------------
__global__ void reset_bar_kernel()
{
    const int i = blockIdx.x * blockDim.x + threadIdx.x;
    if (i < NCTA * FLAG_STRIDE) g_flag[i] = 0u;
}

// ---------------------------------------------------------------------------
// Kernel 3: persistent LSTM recurrence — 32 hidden-groups x 4 batch-groups,
// WARP-SPECIALIZED: 288 threads = 8 dot warps + 1 stager warp.
//
// Stager warp (warp 8), per step:
//   * each lane polls ITS OWN producer's flag (32 lanes <-> 32 producers:
//     parallel detection, straggler costs one L2 round trip, not a scan)
//   * copies h(t-1) in 16 chunks of 32 columns, LDG->reg->STS pipelined
//     depth 4, releasing a per-chunk smem ready flag (st.release.cta) as
//     each chunk lands.
// Dot warps consume chunks in the same CTA-staggered order, gating each
// 32-col k-range on ld.acquire.cta.shared (~30 cyc when ready). Staging
// latency + producer lateness thus overlap the 4096-cyc dot instead of
// preceding it. Ready flags are monotonic step values (no reset races);
// the stager joins both per-step __syncthreads, making single-buffered hs
// write-before-read by construction.
// ---------------------------------------------------------------------------
#define NBG  16           // batches per batch-group
#define WSL  516          // per-slice stride (512 + 4 floats)
#define HSL  516          // per-h-row stride
#define GSL  68           // gate staging row stride (4 gates * 17)
#define NTH  288          // 8 dot warps + 1 stager warp

#define SM_W   (64 * WSL)                 // 33024 floats
#define SM_H   (NBG * HSL)                // 8256
#define SM_G   (NBG * GSL)                // 1088
#define SM_FLOATS (SM_W + SM_H + SM_G)    // 42368
#define SM_BYTES  (SM_FLOATS * 4)         // 169472

__device__ __forceinline__ float sigmoidf_(float v)
{
    return 1.f / (1.f + expf(-v));
}

__global__ __launch_bounds__(NTH, 1)
void lstm_kernel(const float* __restrict__ Whh, float* __restrict__ y)
{
    extern __shared__ float sm[];
    float* __restrict__ wsT = sm;               // [64 slices][WSL]
    float* __restrict__ hs  = sm + SM_W;        // [NBG][HSL]
    float* __restrict__ gs  = sm + SM_W + SM_H; // [NBG][GSL]
    __shared__ int ready16[16];                 // per-chunk staged-step flags

    const int tid  = threadIdx.x;
    const int b    = blockIdx.x;
    const int bg   = b & 3;                // batch group
    const int hg   = b >> 2;               // hidden group
    const int hc0  = hg * 16;              // first h-col owned
    const int nb0  = bg * NBG;             // first batch owned
    const int warp = tid >> 5;
    const int lane = tid & 31;
    const bool is_dot = (tid < 256);

    if (tid < 16) ready16[tid] = 0;

    // ---- load W_hh slices into smem (permuted slice order), one-time
    for (int i = tid; i < 64 * 512; i += NTH) {
        const int k  = i & 511;
        const int p  = i >> 9;             // slice position 0..63
        const int pg = p >> 4;             // gate type
        const int ii = (p & 15) >> 2;
        const int pc = p & 3;
        const int jj = pc * 4 + ii;        // local h-col
        wsT[p * WSL + k] = Whh[(size_t)k * G4 + pg * HH + hc0 + jj];
    }

    // ---- dot-phase mapping (warps 0..7 only; harmless for stager)
    const int n_local = (lane & 7) | ((warp & 1) << 3);     // 0..15
    const int c43     = lane >> 3;                          // 0..3
    const int gt      = (warp >> 1) & 3;                    // 0..3 gate type
    const int jj0     = c43 * 4;                            // first local col

    const float* __restrict__ wp0 = &wsT[(gt * 16 + 0 * 4 + c43) * WSL];
    const float* __restrict__ wp1 = &wsT[(gt * 16 + 1 * 4 + c43) * WSL];
    const float* __restrict__ wp2 = &wsT[(gt * 16 + 2 * 4 + c43) * WSL];
    const float* __restrict__ wp3 = &wsT[(gt * 16 + 3 * 4 + c43) * WSL];
    const float* __restrict__ hrow = &hs[n_local * HSL];

    // ---- activation-phase mapping (tid < 256)
    const int n3 = (tid >> 4) & 15;
    const int j3 = tid & 15;
    float creg = 0.f;                      // c state for (nb0+n3, hc0+j3)

    unsigned* const myflag = &g_flag[b * FLAG_STRIDE];
    const int c0 = ((hg >> 1) + 1) & 15;   // chunk start offset (destagger)

    __syncthreads();

    for (int tstep = 0; tstep < TT; tstep++) {
        if (is_dot) {
            // ---- prefetch this step's input-projection gates
            const float4 xv = *(const float4*)(g_xh +
                ((size_t)tstep * NB + nb0 + n_local) * G4 + gt * HH + hc0 + jj0);

            // ---- dot, chunk-gated on stager's ready flags
            u64 acc0 = 0ull, acc1 = 0ull, acc2v = 0ull, acc3 = 0ull;
            if (tstep > 0) {
                for (int ci = 0; ci < 16; ci++) {
                    const int c = (c0 + ci) & 15;
                    const unsigned ra =
                        (unsigned)__cvta_generic_to_shared(&ready16[c]);
                    int v;
                    do {
                        asm volatile("ld.acquire.cta.shared.s32 %0, [%1];"
                                     : "=r"(v) : "r"(ra) : "memory");
                    } while (v < tstep);
                    const int kb = c * 32;
#pragma unroll
                    for (int kk = 0; kk < 32; kk += 4) {
                        const int k = kb + kk;
                        const ulonglong2 hp = *(const ulonglong2*)(hrow + k);
                        const ulonglong2 w0 = *(const ulonglong2*)(wp0 + k);
                        const ulonglong2 w1 = *(const ulonglong2*)(wp1 + k);
                        const ulonglong2 w2 = *(const ulonglong2*)(wp2 + k);
                        const ulonglong2 w3 = *(const ulonglong2*)(wp3 + k);
                        ffma2(acc0, hp.x, w0.x); ffma2(acc0, hp.y, w0.y);
                        ffma2(acc1, hp.x, w1.x); ffma2(acc1, hp.y, w1.y);
                        ffma2(acc2v, hp.x, w2.x); ffma2(acc2v, hp.y, w2.y);
                        ffma2(acc3, hp.x, w3.x); ffma2(acc3, hp.y, w3.y);
                    }
                }
            }

            // horizontal pair-reduce + prefetched input gates
            {
                const float2 s0 = unpk(acc0), s1 = unpk(acc1);
                const float2 s2 = unpk(acc2v), s3 = unpk(acc3);
                float* g = &gs[n_local * GSL + gt * 17 + jj0];
                g[0] = s0.x + s0.y + xv.x;
                g[1] = s1.x + s1.y + xv.y;
                g[2] = s2.x + s2.y + xv.z;
                g[3] = s3.x + s3.y + xv.w;
            }
        } else if (tstep > 0) {
            // ================= stager warp =================
            // 1) parallel producer-flag poll: lane l waits on producer hg'=l
            {
                unsigned* pf = &g_flag[((lane << 2) | bg) * FLAG_STRIDE];
                unsigned v;
                do {
                    asm volatile("ld.acquire.gpu.u32 %0, [%1];"
                                 : "=r"(v) : "l"(pf) : "memory");
                } while (v < (unsigned)tstep);
            }
            __syncwarp();

            // 2) copy h(t-1): 16 chunks of 32 cols, depth-4 LDG pipeline
            const int row = lane >> 1, half = lane & 1;
            const float* __restrict__ srow = y +
                (size_t)(nb0 + row) * TT * HH + (size_t)(tstep - 1) * HH +
                half * 16;
            float* __restrict__ drow = &hs[row * HSL + half * 16];

            for (int g4i = 0; g4i < 4; g4i++) {
                float4 buf[4][4];
#pragma unroll
                for (int j = 0; j < 4; j++) {
                    const int c = (c0 + g4i * 4 + j) & 15;
                    const float4* s = (const float4*)(srow + c * 32);
                    buf[j][0] = s[0]; buf[j][1] = s[1];
                    buf[j][2] = s[2]; buf[j][3] = s[3];
                }
#pragma unroll
                for (int j = 0; j < 4; j++) {
                    const int c = (c0 + g4i * 4 + j) & 15;
                    float4* d = (float4*)(drow + c * 32);
                    d[0] = buf[j][0]; d[1] = buf[j][1];
                    d[2] = buf[j][2]; d[3] = buf[j][3];
                    __syncwarp();
                    if (lane == 0) {
                        const unsigned ra =
                            (unsigned)__cvta_generic_to_shared(&ready16[c]);
                        asm volatile("st.release.cta.shared.s32 [%0], %1;"
                                     :: "r"(ra), "r"(tstep) : "memory");
                    }
                }
            }
        }
        __syncthreads();   // gates staged; hs consumption complete

        // ---- activations: one output column per thread (tid < 256)
        if (is_dot) {
            const float* g = &gs[n3 * GSL];
            const float gi = g[0  + j3];
            const float gf = g[17 + j3];
            const float gc = g[34 + j3];
            const float go = g[51 + j3];
            const float iv = sigmoidf_(gi);
            const float fv = sigmoidf_(gf);
            const float gv = tanhf(gc);
            const float ov = sigmoidf_(go);
            creg = fv * creg + iv * gv;
            const float hv = ov * tanhf(creg);
            y[(size_t)(nb0 + n3) * TT * HH + (size_t)tstep * HH + hc0 + j3] = hv;
        }
        __syncthreads();   // all y stores done before the release below

        if (tstep < TT - 1 && tid == 0) {
            asm volatile("st.release.gpu.u32 [%0], %1;"
                         :: "l"(myflag), "r"((unsigned)(tstep + 1))
                         : "memory");
        }
    }
}

// ---------------------------------------------------------------------------
// Launch
// ---------------------------------------------------------------------------
extern "C" void kernel_launch(void* const* d_in, const int* in_sizes, int n_in,
                              void* d_out, int out_size)
{
    const float* x   = (const float*)d_in[0];   // (64, 512, 512)
    const float* Wxh = (const float*)d_in[1];   // (512, 2048)
    const float* Whh = (const float*)d_in[2];   // (512, 2048)
    const float* bxh = (const float*)d_in[3];   // (2048,)
    const float* bhh = (const float*)d_in[4];   // (2048,)
    float* y = (float*)d_out;                   // (64, 512, 512)

    // opt-in to >48KB dynamic smem (idempotent host call, capture-safe)
    cudaFuncSetAttribute(lstm_kernel,
                         cudaFuncAttributeMaxDynamicSharedMemorySize, SM_BYTES);

    // flag reset must precede the persistent kernel each call (graph replays)
    reset_bar_kernel<<<8, 512>>>();

    dim3 ggrid(G4 / BN, (TT * NB) / BM);        // (16, 256)
    gemm_xh_kernel<<<ggrid, 256>>>(x, Wxh, bxh, bhh);

    lstm_kernel<<<NCTA, NTH, SM_BYTES>>>(Whh, y);
}

// round 11
// speedup vs baseline: 1.8019x; 1.8019x over previous
#include <cuda_runtime.h>
#include <cuda_bf16.h>
#include <math.h>

// Problem constants
#define NB   64     // batch
#define TT   512    // time steps
#define DD   512    // input dim
#define HH   512    // hidden dim
#define G4   2048   // 4*H

typedef unsigned long long u64;

// ---------------------------------------------------------------------------
// Packed f32x2 helpers (sm_103a FFMA2 — ptxas never auto-generates these)
// ---------------------------------------------------------------------------
__device__ __forceinline__ u64 pack_dup(float v)
{
    u64 r; asm("mov.b64 %0, {%1, %1};" : "=l"(r) : "f"(v)); return r;
}
__device__ __forceinline__ void ffma2(u64& acc, u64 a, u64 b)
{
    asm("fma.rn.f32x2 %0, %1, %2, %0;" : "+l"(acc) : "l"(a), "l"(b));
}
__device__ __forceinline__ float2 unpk(u64 v)
{
    float2 r; asm("mov.b64 {%0, %1}, %2;" : "=f"(r.x), "=f"(r.y) : "l"(v)); return r;
}

// ---------------------------------------------------------------------------
// Scratch (device globals: the sanctioned no-alloc workaround)
// ---------------------------------------------------------------------------
#define NCTA 128
#define FLAG_STRIDE 32   // 128B between flags -> distinct L2 lines/slices

__device__ float    g_xh[(size_t)TT * NB * G4];   // (T, N, 4H) pre-projected gates
__device__ unsigned g_flag[NCTA * FLAG_STRIDE];   // per-CTA step flags, padded

// ---------------------------------------------------------------------------
// Kernel 1: xh = x @ W_xh + (b_xh + b_hh)   — FFMA2 inner loop.
// Block (0,0) additionally zeroes the step flags (replaces the old reset
// kernel: gemm always precedes lstm, kernel boundary gives visibility).
// ---------------------------------------------------------------------------
#define BM 128
#define BN 128
#define BK 8

__global__ __launch_bounds__(256, 2)
void gemm_xh_kernel(const float* __restrict__ x,
                    const float* __restrict__ Wxh,
                    const float* __restrict__ bxh,
                    const float* __restrict__ bhh)
{
    __shared__ float As[BK][BM];   // transposed A tile
    __shared__ float Bs[BK][BN];

    const int tid = threadIdx.x;
    const int bm  = blockIdx.y;
    const int bn  = blockIdx.x;

    // flag reset folded in (keeps graph replays deterministic)
    if (bm == 0 && bn == 0) {
        for (int i = tid; i < NCTA * FLAG_STRIDE; i += 256) g_flag[i] = 0u;
    }

    const int warp = tid >> 5, lane = tid & 31;
    const int wm = warp >> 1, wn = warp & 1;
    const int tm = lane & 3,  tn = lane >> 2;
    const int m0 = wm * 32 + tm * 8;
    const int n0 = wn * 64 + tn * 8;

    const int ar = tid >> 1;
    const int aq = tid & 1;
    const int gm = bm * BM + ar;            // global row m = t*64+n
    const int t  = gm >> 6;
    const int nn = gm & 63;
    const float* __restrict__ arow = x + ((size_t)nn * TT + t) * DD;

    const int rb = tid >> 5;
    const int cb = (tid & 31) * 4;
    const float* __restrict__ bcol = Wxh + (size_t)bn * BN + cb;

    u64 acc2[8][4];
#pragma unroll
    for (int i = 0; i < 8; i++)
#pragma unroll
        for (int j = 0; j < 4; j++) acc2[i][j] = 0ull;

    for (int k0 = 0; k0 < DD; k0 += BK) {
        const float4 av = *(const float4*)(arow + k0 + aq * 4);
        const float4 bv = *(const float4*)(bcol + (size_t)(k0 + rb) * G4);
        __syncthreads();
        As[aq * 4 + 0][ar] = av.x;
        As[aq * 4 + 1][ar] = av.y;
        As[aq * 4 + 2][ar] = av.z;
        As[aq * 4 + 3][ar] = av.w;
        *(float4*)&Bs[rb][cb] = bv;
        __syncthreads();

#pragma unroll
        for (int kk = 0; kk < BK; kk++) {
            float ra[8];
            *(float4*)&ra[0] = *(const float4*)&As[kk][m0];
            *(float4*)&ra[4] = *(const float4*)&As[kk][m0 + 4];
            const ulonglong2 b01 = *(const ulonglong2*)&Bs[kk][n0];
            const ulonglong2 b23 = *(const ulonglong2*)&Bs[kk][n0 + 4];
#pragma unroll
            for (int i = 0; i < 8; i++) {
                const u64 ai = pack_dup(ra[i]);
                ffma2(acc2[i][0], ai, b01.x);
                ffma2(acc2[i][1], ai, b01.y);
                ffma2(acc2[i][2], ai, b23.x);
                ffma2(acc2[i][3], ai, b23.y);
            }
        }
    }

    const int col0 = bn * BN + n0;
    float bsum[8];
#pragma unroll
    for (int j = 0; j < 8; j++)
        bsum[j] = bxh[col0 + j] + bhh[col0 + j];

#pragma unroll
    for (int i = 0; i < 8; i++) {
        const size_t row = (size_t)(bm * BM + m0 + i);
        float* p = g_xh + row * G4 + col0;
        float2 c0 = unpk(acc2[i][0]);
        float2 c1 = unpk(acc2[i][1]);
        float2 c2 = unpk(acc2[i][2]);
        float2 c3 = unpk(acc2[i][3]);
        float4 v0 = make_float4(c0.x + bsum[0], c0.y + bsum[1],
                                c1.x + bsum[2], c1.y + bsum[3]);
        float4 v1 = make_float4(c2.x + bsum[4], c2.y + bsum[5],
                                c3.x + bsum[6], c3.y + bsum[7]);
        *(float4*)p       = v0;
        *(float4*)(p + 4) = v1;
    }
}

// ---------------------------------------------------------------------------
// Kernel 2: persistent LSTM recurrence — 32 hidden-groups x 4 batch-groups
// (R8 structure: all-warp coalesced staging, 32-CTA group flag barriers).
// NEW mapping: thread (n_local, jcol) computes ALL FOUR gates for its one
// output column -> activation + c-state + y store entirely in registers:
// no gate-staging smem roundtrip, one less __syncthreads per step (3 total).
// W smem: 64 k-contiguous slices, slice p = g*16 + j (identity). Per warp:
// 4 consecutive j-slices -> banks +0/+4/+8/+12 (conflict-free broadcast);
// h rows 516-stride -> 8 rows cover all 32 banks (conflict-free).
// Dot engine: FFMA2, k-paired, 13 instr / 4 k, fma-issue-bound (chip floor
// for this decomposition: 4096 cyc/step).
// ---------------------------------------------------------------------------
#define NBG  16           // batches per batch-group
#define WSL  516          // per-slice stride (512 + 4 floats)
#define HSL  516          // per-h-row stride

#define SM_W   (64 * WSL)                 // 33024 floats
#define SM_H   (NBG * HSL)                // 8256
#define SM_BYTES  ((SM_W + SM_H) * 4)     // 165120

__device__ __forceinline__ float fsigmoid_(float v)
{
    return 1.f / (1.f + __expf(-v));
}
__device__ __forceinline__ float ftanh_(float v)
{
    return 1.f - 2.f / (1.f + __expf(2.f * v));
}

__global__ __launch_bounds__(256, 1)
void lstm_kernel(const float* __restrict__ Whh, float* __restrict__ y)
{
    extern __shared__ float sm[];
    float* __restrict__ wsT = sm;               // [64 slices][WSL]
    float* __restrict__ hs  = sm + SM_W;        // [NBG][HSL]

    const int tid  = threadIdx.x;
    const int b    = blockIdx.x;
    const int bg   = b & 3;                // batch group
    const int hg   = b >> 2;               // hidden group
    const int hc0  = hg * 16;              // first h-col owned
    const int nb0  = bg * NBG;             // first batch owned
    const int warp = tid >> 5;
    const int lane = tid & 31;

    // ---- load W_hh slices into smem: slice p = g*16 + j, k-contiguous
    for (int i = tid; i < 64 * 512; i += 256) {
        const int k = i & 511;
        const int p = i >> 9;              // 0..63
        const int g = p >> 4;              // gate type
        const int j = p & 15;              // local h-col
        wsT[p * WSL + k] = Whh[(size_t)k * G4 + g * HH + hc0 + j];
    }

    // ---- mapping: thread -> (n_local, jcol), all 4 gates
    const int n_local = (lane & 7) | ((warp & 1) << 3);     // 0..15
    const int jcol    = ((warp >> 1) << 2) | (lane >> 3);   // 0..15

    const float* __restrict__ wp0 = &wsT[(0 * 16 + jcol) * WSL];
    const float* __restrict__ wp1 = &wsT[(1 * 16 + jcol) * WSL];
    const float* __restrict__ wp2 = &wsT[(2 * 16 + jcol) * WSL];
    const float* __restrict__ wp3 = &wsT[(3 * 16 + jcol) * WSL];
    const float* __restrict__ hrow = &hs[n_local * HSL];

    float creg = 0.f;                      // c state for (nb0+n_local, hc0+jcol)
    float* const yout = y + (size_t)(nb0 + n_local) * TT * HH + hc0 + jcol;
    const float* const xbase = g_xh + (size_t)(nb0 + n_local) * G4 + hc0 + jcol;

    unsigned* const myflag   = &g_flag[b * FLAG_STRIDE];
    unsigned* const pollflag = &g_flag[(((tid & 31) << 2) | bg) * FLAG_STRIDE];

    __syncthreads();

    for (int tstep = 0; tstep < TT; tstep++) {
        // ---- prefetch this step's input-projection gates (4 scalars)
        const float* xp = xbase + (size_t)tstep * NB * G4;
        const float xv0 = xp[0 * HH];
        const float xv1 = xp[1 * HH];
        const float xv2 = xp[2 * HH];
        const float xv3 = xp[3 * HH];

        if (tstep > 0) {
            // ---- group barrier wait: our 32 CTAs finished step tstep-1
            if (tid < 32) {
                const unsigned want = (unsigned)tstep;
                unsigned v;
                do {
                    asm volatile("ld.acquire.gpu.u32 %0, [%1];"
                                 : "=r"(v) : "l"(pollflag) : "memory");
                } while (v < want);
            }
            __syncthreads();

            // ---- stage h(t-1) for our 16 batches: warp copies 2 rows
            const size_t tb = (size_t)(tstep - 1) * HH;
#pragma unroll
            for (int r2 = 0; r2 < 2; r2++) {
                const int row = warp * 2 + r2;
                const float4* __restrict__ src =
                    (const float4*)(y + (size_t)(nb0 + row) * TT * HH + tb);
                float4* __restrict__ dst = (float4*)&hs[row * HSL];
#pragma unroll
                for (int p = 0; p < 4; p++)
                    dst[lane + p * 32] = src[lane + p * 32];
            }
        }
        __syncthreads();

        // ---- dot: all 4 gates for (n_local, jcol)
        u64 acc0 = 0ull, acc1 = 0ull, acc2v = 0ull, acc3 = 0ull;
        if (tstep > 0) {
#pragma unroll 8
            for (int k = 0; k < HH; k += 4) {
                const ulonglong2 hp = *(const ulonglong2*)(hrow + k);
                const ulonglong2 w0 = *(const ulonglong2*)(wp0 + k);
                const ulonglong2 w1 = *(const ulonglong2*)(wp1 + k);
                const ulonglong2 w2 = *(const ulonglong2*)(wp2 + k);
                const ulonglong2 w3 = *(const ulonglong2*)(wp3 + k);
                ffma2(acc0, hp.x, w0.x); ffma2(acc0, hp.y, w0.y);
                ffma2(acc1, hp.x, w1.x); ffma2(acc1, hp.y, w1.y);
                ffma2(acc2v, hp.x, w2.x); ffma2(acc2v, hp.y, w2.y);
                ffma2(acc3, hp.x, w3.x); ffma2(acc3, hp.y, w3.y);
            }
        }

        // ---- reduce + activations + store, all in registers
        {
            const float2 s0 = unpk(acc0), s1 = unpk(acc1);
            const float2 s2 = unpk(acc2v), s3 = unpk(acc3);
            const float gi = s0.x + s0.y + xv0;
            const float gf = s1.x + s1.y + xv1;
            const float gc = s2.x + s2.y + xv2;
            const float go = s3.x + s3.y + xv3;
            const float iv = fsigmoid_(gi);
            const float fv = fsigmoid_(gf);
            const float gv = ftanh_(gc);
            const float ov = fsigmoid_(go);
            creg = fv * creg + iv * gv;
            yout[(size_t)tstep * HH] = ov * ftanh_(creg);
        }
        __syncthreads();   // all y stores + hs consumption done

        if (tstep < TT - 1 && tid == 0) {
            // group barrier arrive: one release store, own slot
            asm volatile("st.release.gpu.u32 [%0], %1;"
                         :: "l"(myflag), "r"((unsigned)(tstep + 1))
                         : "memory");
        }
    }
}

// ---------------------------------------------------------------------------
// Launch
// ---------------------------------------------------------------------------
extern "C" void kernel_launch(void* const* d_in, const int* in_sizes, int n_in,
                              void* d_out, int out_size)
{
    const float* x   = (const float*)d_in[0];   // (64, 512, 512)
    const float* Wxh = (const float*)d_in[1];   // (512, 2048)
    const float* Whh = (const float*)d_in[2];   // (512, 2048)
    const float* bxh = (const float*)d_in[3];   // (2048,)
    const float* bhh = (const float*)d_in[4];   // (2048,)
    float* y = (float*)d_out;                   // (64, 512, 512)

    // opt-in to >48KB dynamic smem (idempotent host call, capture-safe)
    cudaFuncSetAttribute(lstm_kernel,
                         cudaFuncAttributeMaxDynamicSharedMemorySize, SM_BYTES);

    dim3 ggrid(G4 / BN, (TT * NB) / BM);        // (16, 256)
    gemm_xh_kernel<<<ggrid, 256>>>(x, Wxh, bxh, bhh);   // also resets flags

    lstm_kernel<<<NCTA, 256, SM_BYTES>>>(Whh, y);
}

// round 15
// speedup vs baseline: 2.1092x; 1.1706x over previous
#include <cuda_runtime.h>
#include <cuda_bf16.h>
#include <math.h>

// Problem constants
#define NB   64     // batch
#define TT   512    // time steps
#define DD   512    // input dim
#define HH   512    // hidden dim
#define G4   2048   // 4*H

typedef unsigned long long u64;

// ---------------------------------------------------------------------------
// Packed f32x2 helpers (sm_103a FFMA2 — ptxas never auto-generates these)
// ---------------------------------------------------------------------------
__device__ __forceinline__ u64 pack_dup(float v)
{
    u64 r; asm("mov.b64 %0, {%1, %1};" : "=l"(r) : "f"(v)); return r;
}
__device__ __forceinline__ void ffma2(u64& acc, u64 a, u64 b)
{
    asm("fma.rn.f32x2 %0, %1, %2, %0;" : "+l"(acc) : "l"(a), "l"(b));
}
__device__ __forceinline__ float2 unpk(u64 v)
{
    float2 r; asm("mov.b64 {%0, %1}, %2;" : "=f"(r.x), "=f"(r.y) : "l"(v)); return r;
}

// ---------------------------------------------------------------------------
// Scratch (device globals: the sanctioned no-alloc workaround)
// ---------------------------------------------------------------------------
#define NCTA 128
#define FLAG_STRIDE 32   // 128B between flags -> distinct L2 lines/slices

__device__ float    g_xh[(size_t)TT * NB * G4];   // (T, N, 4H) pre-projected gates
__device__ unsigned g_flag[NCTA * FLAG_STRIDE];   // per-CTA step flags, padded

// ---------------------------------------------------------------------------
// Kernel 1: xh = x @ W_xh + (b_xh + b_hh)   — FFMA2 inner loop.
// Block (0,0) additionally zeroes the step flags.
// ---------------------------------------------------------------------------
#define BM 128
#define BN 128
#define BK 8

__global__ __launch_bounds__(256, 2)
void gemm_xh_kernel(const float* __restrict__ x,
                    const float* __restrict__ Wxh,
                    const float* __restrict__ bxh,
                    const float* __restrict__ bhh)
{
    __shared__ float As[BK][BM];   // transposed A tile
    __shared__ float Bs[BK][BN];

    const int tid = threadIdx.x;
    const int bm  = blockIdx.y;
    const int bn  = blockIdx.x;

    // flag reset folded in (keeps graph replays deterministic)
    if (bm == 0 && bn == 0) {
        for (int i = tid; i < NCTA * FLAG_STRIDE; i += 256) g_flag[i] = 0u;
    }

    const int warp = tid >> 5, lane = tid & 31;
    const int wm = warp >> 1, wn = warp & 1;
    const int tm = lane & 3,  tn = lane >> 2;
    const int m0 = wm * 32 + tm * 8;
    const int n0 = wn * 64 + tn * 8;

    const int ar = tid >> 1;
    const int aq = tid & 1;
    const int gm = bm * BM + ar;            // global row m = t*64+n
    const int t  = gm >> 6;
    const int nn = gm & 63;
    const float* __restrict__ arow = x + ((size_t)nn * TT + t) * DD;

    const int rb = tid >> 5;
    const int cb = (tid & 31) * 4;
    const float* __restrict__ bcol = Wxh + (size_t)bn * BN + cb;

    u64 acc2[8][4];
#pragma unroll
    for (int i = 0; i < 8; i++)
#pragma unroll
        for (int j = 0; j < 4; j++) acc2[i][j] = 0ull;

    for (int k0 = 0; k0 < DD; k0 += BK) {
        const float4 av = *(const float4*)(arow + k0 + aq * 4);
        const float4 bv = *(const float4*)(bcol + (size_t)(k0 + rb) * G4);
        __syncthreads();
        As[aq * 4 + 0][ar] = av.x;
        As[aq * 4 + 1][ar] = av.y;
        As[aq * 4 + 2][ar] = av.z;
        As[aq * 4 + 3][ar] = av.w;
        *(float4*)&Bs[rb][cb] = bv;
        __syncthreads();

#pragma unroll
        for (int kk = 0; kk < BK; kk++) {
            float ra[8];
            *(float4*)&ra[0] = *(const float4*)&As[kk][m0];
            *(float4*)&ra[4] = *(const float4*)&As[kk][m0 + 4];
            const ulonglong2 b01 = *(const ulonglong2*)&Bs[kk][n0];
            const ulonglong2 b23 = *(const ulonglong2*)&Bs[kk][n0 + 4];
#pragma unroll
            for (int i = 0; i < 8; i++) {
                const u64 ai = pack_dup(ra[i]);
                ffma2(acc2[i][0], ai, b01.x);
                ffma2(acc2[i][1], ai, b01.y);
                ffma2(acc2[i][2], ai, b23.x);
                ffma2(acc2[i][3], ai, b23.y);
            }
        }
    }

    const int col0 = bn * BN + n0;
    float bsum[8];
#pragma unroll
    for (int j = 0; j < 8; j++)
        bsum[j] = bxh[col0 + j] + bhh[col0 + j];

#pragma unroll
    for (int i = 0; i < 8; i++) {
        const size_t row = (size_t)(bm * BM + m0 + i);
        float* p = g_xh + row * G4 + col0;
        float2 c0 = unpk(acc2[i][0]);
        float2 c1 = unpk(acc2[i][1]);
        float2 c2 = unpk(acc2[i][2]);
        float2 c3 = unpk(acc2[i][3]);
        float4 v0 = make_float4(c0.x + bsum[0], c0.y + bsum[1],
                                c1.x + bsum[2], c1.y + bsum[3]);
        float4 v1 = make_float4(c2.x + bsum[4], c2.y + bsum[5],
                                c3.x + bsum[6], c3.y + bsum[7]);
        *(float4*)p       = v0;
        *(float4*)(p + 4) = v1;
    }
}

// ---------------------------------------------------------------------------
// Kernel 2: persistent LSTM recurrence — 32 hidden-groups x 4 batch-groups.
// (R11 was LDS-bound: L1=65.6%, fma=20.9%.) 2-batch register blocking with
// k-SPLIT across warp halves:
//   warps 0-3: k in [0,256);  warps 4-7: k in [256,512)
//   thread = (kh = warp>>2, jq = warp&3, np = lane&7, jlo = lane>>3)
//   computes partial gates for n in {np, np+8}, all 4 gates, col j=jq*4+jlo.
// LDS per warp per 4k: 2 h (128B, 1 wf each: 8 rows stride 516 -> banks 4np)
// + 4 w (64B, 1 wf: 4 consecutive slices -> banks +0/4/8/12) = 6 wf over 64
// iters = 3072 wf/SM/step (was ~5100) -> FFMA2-issue (4096 cyc) binds again.
// k-half partners (tid^128) exchange 4 partial sums via padded smem
// (stride 5 -> bank permutation), one extra __syncthreads.
// ---------------------------------------------------------------------------
#define NBG  16           // batches per batch-group
#define WSL  516          // per-slice stride (512 + 4 floats)
#define HSL  516          // per-h-row stride
#define KHALF 256         // k per warp-half

#define SM_W   (64 * WSL)                 // 33024 floats
#define SM_H   (NBG * HSL)                // 8256
#define SM_R   (256 * 5)                  // 1280 (partial-exchange, pad 5)
#define SM_BYTES  ((SM_W + SM_H + SM_R) * 4)   // 170240

__device__ __forceinline__ float fsigmoid_(float v)
{
    return 1.f / (1.f + __expf(-v));
}
__device__ __forceinline__ float ftanh_(float v)
{
    return 1.f - 2.f / (1.f + __expf(2.f * v));
}

__global__ __launch_bounds__(256, 1)
void lstm_kernel(const float* __restrict__ Whh, float* __restrict__ y)
{
    extern __shared__ float sm[];
    float* __restrict__ wsT = sm;                    // [64 slices][WSL]
    float* __restrict__ hs  = sm + SM_W;             // [NBG][HSL]
    float* __restrict__ red = sm + SM_W + SM_H;      // [256][5]

    const int tid  = threadIdx.x;
    const int b    = blockIdx.x;
    const int bg   = b & 3;                // batch group
    const int hg   = b >> 2;               // hidden group
    const int hc0  = hg * 16;              // first h-col owned
    const int nb0  = bg * NBG;             // first batch owned
    const int warp = tid >> 5;
    const int lane = tid & 31;

    // ---- load W_hh slices into smem: slice p = g*16 + j, k-contiguous
    for (int i = tid; i < 64 * 512; i += 256) {
        const int k = i & 511;
        const int p = i >> 9;              // 0..63
        const int g = p >> 4;              // gate type
        const int j = p & 15;              // local h-col
        wsT[p * WSL + k] = Whh[(size_t)k * G4 + g * HH + hc0 + j];
    }

    // ---- dot mapping
    const int kh  = warp >> 2;             // k-half 0/1
    const int jq  = warp & 3;              // j quad
    const int np  = lane & 7;              // batch pair base 0..7
    const int jlo = lane >> 3;             // 0..3
    const int j   = jq * 4 + jlo;          // 0..15
    const int k0  = kh * KHALF;

    const float* __restrict__ wp0 = &wsT[(0 * 16 + j) * WSL + k0];
    const float* __restrict__ wp1 = &wsT[(1 * 16 + j) * WSL + k0];
    const float* __restrict__ wp2 = &wsT[(2 * 16 + j) * WSL + k0];
    const float* __restrict__ wp3 = &wsT[(3 * 16 + j) * WSL + k0];
    const float* __restrict__ hr0 = &hs[np * HSL + k0];
    const float* __restrict__ hr1 = &hs[(np + 8) * HSL + k0];

    // ---- activation assignment: this thread owns (n_act, j)
    const int n_act = np + 8 * kh;
    float creg = 0.f;
    float* const yout = y + (size_t)(nb0 + n_act) * TT * HH + hc0 + j;
    const float* const xbase = g_xh + (size_t)(nb0 + n_act) * G4 + hc0 + j;

    float* const redw = &red[tid * 5];                 // my export slot
    const float* const redr = &red[(tid ^ 128) * 5];   // partner's slot

    unsigned* const myflag   = &g_flag[b * FLAG_STRIDE];
    unsigned* const pollflag = &g_flag[(((tid & 31) << 2) | bg) * FLAG_STRIDE];

    __syncthreads();

    for (int tstep = 0; tstep < TT; tstep++) {
        // ---- prefetch this step's input-projection gates (4 scalars)
        const float* xp = xbase + (size_t)tstep * NB * G4;
        const float xv0 = xp[0 * HH];
        const float xv1 = xp[1 * HH];
        const float xv2 = xp[2 * HH];
        const float xv3 = xp[3 * HH];

        if (tstep > 0) {
            // ---- group barrier wait: our 32 CTAs finished step tstep-1
            if (tid < 32) {
                const unsigned want = (unsigned)tstep;
                unsigned v;
                do {
                    asm volatile("ld.acquire.gpu.u32 %0, [%1];"
                                 : "=r"(v) : "l"(pollflag) : "memory");
                } while (v < want);
            }
            __syncthreads();

            // ---- stage h(t-1) for our 16 batches: warp copies 2 rows
            const size_t tb = (size_t)(tstep - 1) * HH;
#pragma unroll
            for (int r2 = 0; r2 < 2; r2++) {
                const int row = warp * 2 + r2;
                const float4* __restrict__ src =
                    (const float4*)(y + (size_t)(nb0 + row) * TT * HH + tb);
                float4* __restrict__ dst = (float4*)&hs[row * HSL];
#pragma unroll
                for (int p = 0; p < 4; p++)
                    dst[lane + p * 32] = src[lane + p * 32];
            }
        }
        __syncthreads();

        // ---- dot: partial gates over this warp's k-half
        u64 a00 = 0ull, a01 = 0ull, a02 = 0ull, a03 = 0ull;  // n = np
        u64 a10 = 0ull, a11 = 0ull, a12 = 0ull, a13 = 0ull;  // n = np+8
        if (tstep > 0) {
#pragma unroll 8
            for (int k = 0; k < KHALF; k += 4) {
                const ulonglong2 hp0 = *(const ulonglong2*)(hr0 + k);
                const ulonglong2 hp1 = *(const ulonglong2*)(hr1 + k);
                const ulonglong2 w0 = *(const ulonglong2*)(wp0 + k);
                const ulonglong2 w1 = *(const ulonglong2*)(wp1 + k);
                const ulonglong2 w2 = *(const ulonglong2*)(wp2 + k);
                const ulonglong2 w3 = *(const ulonglong2*)(wp3 + k);
                ffma2(a00, hp0.x, w0.x); ffma2(a00, hp0.y, w0.y);
                ffma2(a01, hp0.x, w1.x); ffma2(a01, hp0.y, w1.y);
                ffma2(a02, hp0.x, w2.x); ffma2(a02, hp0.y, w2.y);
                ffma2(a03, hp0.x, w3.x); ffma2(a03, hp0.y, w3.y);
                ffma2(a10, hp1.x, w0.x); ffma2(a10, hp1.y, w0.y);
                ffma2(a11, hp1.x, w1.x); ffma2(a11, hp1.y, w1.y);
                ffma2(a12, hp1.x, w2.x); ffma2(a12, hp1.y, w2.y);
                ffma2(a13, hp1.x, w3.x); ffma2(a13, hp1.y, w3.y);
            }
        }

        // ---- horizontal reduce: s[ni][g]
        float s00, s01, s02, s03, s10, s11, s12, s13;
        {
            float2 t2;
            t2 = unpk(a00); s00 = t2.x + t2.y;
            t2 = unpk(a01); s01 = t2.x + t2.y;
            t2 = unpk(a02); s02 = t2.x + t2.y;
            t2 = unpk(a03); s03 = t2.x + t2.y;
            t2 = unpk(a10); s10 = t2.x + t2.y;
            t2 = unpk(a11); s11 = t2.x + t2.y;
            t2 = unpk(a12); s12 = t2.x + t2.y;
            t2 = unpk(a13); s13 = t2.x + t2.y;
        }

        // ---- export the half my partner consumes (n = np + 8*(1-kh))
        if (kh == 0) {
            redw[0] = s10; redw[1] = s11; redw[2] = s12; redw[3] = s13;
        } else {
            redw[0] = s00; redw[1] = s01; redw[2] = s02; redw[3] = s03;
        }
        __syncthreads();

        // ---- combine with partner's partials for my n_act, activate, store
        {
            float m0, m1, m2, m3;
            if (kh == 0) { m0 = s00; m1 = s01; m2 = s02; m3 = s03; }
            else         { m0 = s10; m1 = s11; m2 = s12; m3 = s13; }
            const float gi = m0 + redr[0] + xv0;
            const float gf = m1 + redr[1] + xv1;
            const float gc = m2 + redr[2] + xv2;
            const float go = m3 + redr[3] + xv3;
            const float iv = fsigmoid_(gi);
            const float fv = fsigmoid_(gf);
            const float gv = ftanh_(gc);
            const float ov = fsigmoid_(go);
            creg = fv * creg + iv * gv;
            yout[(size_t)tstep * HH] = ov * ftanh_(creg);
        }
        __syncthreads();   // y stores + red reads done before release/reuse

        if (tstep < TT - 1 && tid == 0) {
            asm volatile("st.release.gpu.u32 [%0], %1;"
                         :: "l"(myflag), "r"((unsigned)(tstep + 1))
                         : "memory");
        }
    }
}

// ---------------------------------------------------------------------------
// Launch
// ---------------------------------------------------------------------------
extern "C" void kernel_launch(void* const* d_in, const int* in_sizes, int n_in,
                              void* d_out, int out_size)
{
    const float* x   = (const float*)d_in[0];   // (64, 512, 512)
    const float* Wxh = (const float*)d_in[1];   // (512, 2048)
    const float* Whh = (const float*)d_in[2];   // (512, 2048)
    const float* bxh = (const float*)d_in[3];   // (2048,)
    const float* bhh = (const float*)d_in[4];   // (2048,)
    float* y = (float*)d_out;                   // (64, 512, 512)

    // opt-in to >48KB dynamic smem (idempotent host call, capture-safe)
    cudaFuncSetAttribute(lstm_kernel,
                         cudaFuncAttributeMaxDynamicSharedMemorySize, SM_BYTES);

    dim3 ggrid(G4 / BN, (TT * NB) / BM);        // (16, 256)
    gemm_xh_kernel<<<ggrid, 256>>>(x, Wxh, bxh, bhh);   // also resets flags

    lstm_kernel<<<NCTA, 256, SM_BYTES>>>(Whh, y);
}